// round 11
// baseline (speedup 1.0000x reference)
#include <cuda_runtime.h>
#include <cuda_fp16.h>
#include <cstdint>

// EncoderGRU B=16384 T=512 I=4 H=64 — fp16 m16n8k16, m32 warps, reg-resident h.
// 128 CTAs x 256 thr (8 warps = 4 pairs = 2/SMSP). Warp PAIR owns 32 batches
// (two m16 frags); each warp owns 32 units (j0..j0+3) => 120 MMAs/warp-step.
// B-fragment LDS amortized over 2x batches (halves L1 bytes/batch).
// A-frags: own 2 k-tiles rebuilt from hold regs (D-frag j == A-frag ktile j/2);
// partner's 2 k-tiles via smem (double-buffered, 1 named bar.sync/step).
// Precision: h_hi fp16 x W_hi fp16, fp32 accum (1-term); x keeps 3-term fold
// in one k16 tile. Gates via tanh.approx. Same math as the 5.9e-5 kernel.

#define T_STEPS 512
#define THREADS 256
#define HP 72   // h row stride (floats)

#define OFF_BB   0u        // u64[24 nt][4 kt][32]   24576
#define OFF_BX   24576u    // u64[16 nt][32]          4096
#define OFF_BXN  28672u    // u64[8 nt][32]           2048
#define OFF_HS   30720u    // float[4 pairs][2][32][HP] 73728
#define OFF_BRZ  104448u   // float[128]
#define OFF_BNH  104960u   // float[64]
#define OFF_BNX  105216u   // float[64]
#define SMEM_TOTAL 105472

#define LO32(u) ((uint32_t)(u))
#define HI32(u) ((uint32_t)((u) >> 32))

__device__ __forceinline__ uint32_t pkh(__half a, __half b) {
    return (uint32_t)*(uint16_t*)&a | ((uint32_t)*(uint16_t*)&b << 16);
}
__device__ __forceinline__ void hsplit2(float a, float b, uint32_t& hi, uint32_t& lo) {
    __half ah = __float2half_rn(a), bh = __float2half_rn(b);
    __half al = __float2half_rn(a - __half2float(ah));
    __half bl = __float2half_rn(b - __half2float(bh));
    hi = pkh(ah, bh);
    lo = pkh(al, bl);
}
__device__ __forceinline__ uint32_t hpack2(float a, float b) {
    __half2 h2 = __floats2half2_rn(a, b);
    return *(uint32_t*)&h2;
}
__device__ __forceinline__ void mma16(float* d, const uint32_t* a, uint32_t b0, uint32_t b1) {
    asm("mma.sync.aligned.m16n8k16.row.col.f32.f16.f16.f32 "
        "{%0,%1,%2,%3}, {%4,%5,%6,%7}, {%8,%9}, {%0,%1,%2,%3};"
        : "+f"(d[0]), "+f"(d[1]), "+f"(d[2]), "+f"(d[3])
        : "r"(a[0]), "r"(a[1]), "r"(a[2]), "r"(a[3]), "r"(b0), "r"(b1));
}
__device__ __forceinline__ float tanh_apx(float v) {
    float y; asm("tanh.approx.f32 %0, %1;" : "=f"(y) : "f"(v)); return y;
}
__device__ __forceinline__ float sig_t(float v) {
    return fmaf(tanh_apx(0.5f * v), 0.5f, 0.5f);
}

__global__ __launch_bounds__(THREADS, 1)
void gru_m32(const float* __restrict__ x, const float* __restrict__ w_ih,
             const float* __restrict__ w_hh, const float* __restrict__ b_ih,
             const float* __restrict__ b_hh, float* __restrict__ out)
{
    extern __shared__ char sm[];
    uint64_t* BB  = (uint64_t*)(sm + OFF_BB);
    uint64_t* BX  = (uint64_t*)(sm + OFF_BX);
    uint64_t* BXN = (uint64_t*)(sm + OFF_BXN);
    float* HS  = (float*)(sm + OFF_HS);
    float* BRZ = (float*)(sm + OFF_BRZ);
    float* BNH = (float*)(sm + OFF_BNH);
    float* BNX = (float*)(sm + OFF_BNX);

    const int tid = threadIdx.x, lane = tid & 31, warp = tid >> 5;

    // ================= one-time init =================
    for (int idx = tid; idx < 24 * 4 * 32; idx += THREADS) {
        int nt = idx >> 7, kt = (idx >> 5) & 3, le = idx & 31;
        int n = nt * 8 + (le >> 2), k0 = kt * 16 + 2 * (le & 3);
        uint32_t h01, l01, h89, l89;
        hsplit2(w_hh[n * 64 + k0],     w_hh[n * 64 + k0 + 1], h01, l01);
        hsplit2(w_hh[n * 64 + k0 + 8], w_hh[n * 64 + k0 + 9], h89, l89);
        BB[idx] = (uint64_t)h01 | ((uint64_t)h89 << 32);
    }
    for (int idx = tid; idx < 16 * 32; idx += THREADS) {
        int nt = idx >> 5, le = idx & 31, c = le & 3;
        int n = nt * 8 + (le >> 2), cc = 2 * (c & 1);
        uint32_t hi, lo;
        hsplit2(w_ih[n * 4 + cc], w_ih[n * 4 + cc + 1], hi, lo);
        BX[idx] = (uint64_t)hi | ((uint64_t)((c < 2) ? lo : 0u) << 32);
    }
    for (int idx = tid; idx < 8 * 32; idx += THREADS) {
        int nt = idx >> 5, le = idx & 31, c = le & 3;
        int n = 128 + nt * 8 + (le >> 2), cc = 2 * (c & 1);
        uint32_t hi, lo;
        hsplit2(w_ih[n * 4 + cc], w_ih[n * 4 + cc + 1], hi, lo);
        BXN[idx] = (uint64_t)hi | ((uint64_t)((c < 2) ? lo : 0u) << 32);
    }
    for (int idx = tid; idx < 4 * 2 * 32 * HP; idx += THREADS) HS[idx] = 0.0f;
    for (int idx = tid; idx < 128; idx += THREADS) BRZ[idx] = b_ih[idx] + b_hh[idx];
    if (tid < 64) { BNH[tid] = b_hh[128 + tid]; BNX[tid] = b_ih[128 + tid]; }
    __syncthreads();

    // ================= per-warp geometry =================
    const int pair = warp >> 1, half = warp & 1;
    const int base = (blockIdx.x * 4 + pair) * 32;
    float* hs0 = HS + pair * (2 * 32 * HP);
    const int g = lane >> 2, c = lane & 3;
    const int u0 = 2 * c, cc = 2 * (c & 1);
    const int j0 = half * 4;                 // own unit-blocks j0..j0+3
    const int pk0 = (1 - half) * 2;          // partner's first k-tile

    // x rows this thread feeds: i = mh*2 + rhalf -> row base + mh*16 + rhalf*8 + g
    const float* xp[4];
    float2 xq[4];
#pragma unroll
    for (int i = 0; i < 4; i++) {
        int row = base + (i >> 1) * 16 + (i & 1) * 8 + g;
        xp[i] = x + (size_t)row * T_STEPS * 4 + cc;
        xq[i] = *(const float2*)xp[i];
    }

    // hold[jj][mh][e]: units {j*8+u0,+1} rows (mh*16+g | +8) — own D-frag state
    float hold[4][2][4];
#pragma unroll
    for (int jj = 0; jj < 4; jj++)
#pragma unroll
        for (int mh = 0; mh < 2; mh++)
#pragma unroll
            for (int e = 0; e < 4; e++) hold[jj][mh][e] = 0.0f;

    uint32_t Ah[4][2][4], Ax[2][4];

    for (int t = 0; t < T_STEPS; t++) {
        const float* hrd = hs0 + (t & 1) * (32 * HP);
        float*       hwr = hs0 + ((t & 1) ^ 1) * (32 * HP);

        // ---- own 2 k-tiles: A-frags straight from hold regs (D->A identity) ----
#pragma unroll
        for (int o = 0; o < 2; o++) {
            const int kt = half * 2 + o;
#pragma unroll
            for (int mh = 0; mh < 2; mh++) {
                Ah[kt][mh][0] = hpack2(hold[2 * o][mh][0],     hold[2 * o][mh][1]);
                Ah[kt][mh][1] = hpack2(hold[2 * o][mh][2],     hold[2 * o][mh][3]);
                Ah[kt][mh][2] = hpack2(hold[2 * o + 1][mh][0], hold[2 * o + 1][mh][1]);
                Ah[kt][mh][3] = hpack2(hold[2 * o + 1][mh][2], hold[2 * o + 1][mh][3]);
            }
        }
        // ---- partner's 2 k-tiles from smem ----
#pragma unroll
        for (int o = 0; o < 2; o++) {
            const int kt = pk0 + o;
#pragma unroll
            for (int mh = 0; mh < 2; mh++) {
                const float* r0 = hrd + (mh * 16 + g) * HP + kt * 16 + u0;
                const float* r8 = r0 + 8 * HP;
                float2 v0 = *(const float2*)r0;
                float2 v8 = *(const float2*)r8;
                float2 w0 = *(const float2*)(r0 + 8);
                float2 w8 = *(const float2*)(r8 + 8);
                Ah[kt][mh][0] = hpack2(v0.x, v0.y);
                Ah[kt][mh][1] = hpack2(v8.x, v8.y);
                Ah[kt][mh][2] = hpack2(w0.x, w0.y);
                Ah[kt][mh][3] = hpack2(w8.x, w8.y);
            }
        }
        // ---- x frags (3-term fold) ----
#pragma unroll
        for (int mh = 0; mh < 2; mh++) {
            uint32_t ha_, la_, hb_, lb_;
            hsplit2(xq[2 * mh].x,     xq[2 * mh].y,     ha_, la_);
            hsplit2(xq[2 * mh + 1].x, xq[2 * mh + 1].y, hb_, lb_);
            Ax[mh][0] = (c < 2) ? ha_ : la_;
            Ax[mh][1] = (c < 2) ? hb_ : lb_;
            Ax[mh][2] = (c < 2) ? ha_ : 0u;
            Ax[mh][3] = (c < 2) ? hb_ : 0u;
        }
        if (t + 1 < T_STEPS) {   // prefetch under MMA latency
#pragma unroll
            for (int i = 0; i < 4; i++)
                xq[i] = *(const float2*)(xp[i] + (size_t)(t + 1) * 4);
        }

        // ---- own 4 unit-blocks x 2 m-halves (fully unrolled: hold in regs) ----
#pragma unroll
        for (int jj = 0; jj < 4; jj++) {
            const int j = j0 + jj;
            float dr[2][4] = {}, dz[2][4] = {}, dn[2][4] = {}, dx[2][4] = {};
#pragma unroll
            for (int kt = 0; kt < 4; kt++) {
                uint64_t br = BB[(j * 4 + kt) * 32 + lane];
                uint64_t bz = BB[((8 + j) * 4 + kt) * 32 + lane];
                uint64_t bn = BB[((16 + j) * 4 + kt) * 32 + lane];
#pragma unroll
                for (int mh = 0; mh < 2; mh++) {
                    mma16(dr[mh], Ah[kt][mh], LO32(br), HI32(br));
                    mma16(dz[mh], Ah[kt][mh], LO32(bz), HI32(bz));
                    mma16(dn[mh], Ah[kt][mh], LO32(bn), HI32(bn));
                }
            }
            {
                uint64_t bxr = BX[j * 32 + lane];
                uint64_t bxz = BX[(8 + j) * 32 + lane];
                uint64_t bxn = BXN[j * 32 + lane];
#pragma unroll
                for (int mh = 0; mh < 2; mh++) {
                    mma16(dr[mh], Ax[mh], LO32(bxr), HI32(bxr));
                    mma16(dz[mh], Ax[mh], LO32(bxz), HI32(bxz));
                    mma16(dx[mh], Ax[mh], LO32(bxn), HI32(bxn));
                }
            }
            // ---- epilogue (old h from regs; write h' for partner's A-frags) ----
            float2 b_r = *(const float2*)(BRZ + j * 8 + u0);
            float2 b_z = *(const float2*)(BRZ + 64 + j * 8 + u0);
            float2 b_h = *(const float2*)(BNH + j * 8 + u0);
            float2 b_x = *(const float2*)(BNX + j * 8 + u0);
#pragma unroll
            for (int mh = 0; mh < 2; mh++) {
#pragma unroll
                for (int e = 0; e < 4; e++) {
                    float brv = (e & 1) ? b_r.y : b_r.x;
                    float bzv = (e & 1) ? b_z.y : b_z.x;
                    float bhv = (e & 1) ? b_h.y : b_h.x;
                    float bxv = (e & 1) ? b_x.y : b_x.x;
                    float r = sig_t(dr[mh][e] + brv);
                    float z = sig_t(dz[mh][e] + bzv);
                    float n = tanh_apx(fmaf(r, dn[mh][e] + bhv, dx[mh][e] + bxv));
                    hold[jj][mh][e] = fmaf(z, hold[jj][mh][e] - n, n);
                }
                float* wa = hwr + (mh * 16 + g) * HP + j * 8 + u0;
                *(float2*)wa            = make_float2(hold[jj][mh][0], hold[jj][mh][1]);
                *(float2*)(wa + 8 * HP) = make_float2(hold[jj][mh][2], hold[jj][mh][3]);
            }
        }

        // pair barrier: h'(t+1) writes visible before next step's partner reads
        asm volatile("bar.sync %0, %1;" :: "r"(pair + 1), "r"(64) : "memory");
    }

    // ---- output straight from hold regs ----
#pragma unroll
    for (int jj = 0; jj < 4; jj++) {
        const int j = j0 + jj;
#pragma unroll
        for (int mh = 0; mh < 2; mh++) {
            const int row = base + mh * 16 + g;
            *(float2*)(out + (size_t)row * 64 + j * 8 + u0) =
                make_float2(hold[jj][mh][0], hold[jj][mh][1]);
            *(float2*)(out + (size_t)(row + 8) * 64 + j * 8 + u0) =
                make_float2(hold[jj][mh][2], hold[jj][mh][3]);
        }
    }
}

extern "C" void kernel_launch(void* const* d_in, const int* in_sizes, int n_in,
                              void* d_out, int out_size)
{
    const float* x    = (const float*)d_in[0];
    const float* w_ih = (const float*)d_in[1];
    const float* w_hh = (const float*)d_in[2];
    const float* b_ih = (const float*)d_in[3];
    const float* b_hh = (const float*)d_in[4];
    float* out = (float*)d_out;

    cudaFuncSetAttribute(gru_m32, cudaFuncAttributeMaxDynamicSharedMemorySize, SMEM_TOTAL);
    gru_m32<<<128, THREADS, SMEM_TOTAL>>>(x, w_ih, w_hh, b_ih, b_hh, out);
}

// round 12
// speedup vs baseline: 1.0636x; 1.0636x over previous
#include <cuda_runtime.h>
#include <cuda_fp16.h>
#include <cstdint>

// EncoderGRU B=16384 T=512 I=4 H=64 — fp16 m16n8k16, QUAD warps, reg-resident h.
// 128 CTAs x 512 thr (16 warps = 4 quads = 4/SMSP). Quad owns 32 batches (two
// m16 frags); warp w4 owns 16 units (j = 2w4, 2w4+1) => 60 MMAs/warp-step
// (same per-SMSP MMA work as the 1081us kernel, ~0.7x the LDS traffic).
// Warp's own j-pair == A k-tile w4 (D->A identity) -> rebuilt from hold regs;
// 3 partner k-tiles via smem (double-buffered, 1 named bar.sync(128)/step).
// A-tile regs stored OWN-FIRST (compile-time index); runtime ktile id only in
// smem addresses. 1-term fp16 h-path + 3-term x fold + tanh.approx gates
// (bit-identical math to the rel_err=5.9e-5 kernel).

#define T_STEPS 512
#define THREADS 512
#define HP 72   // h row stride (floats)

#define OFF_BB   0u        // u64[24 nt][4 kt][32]   24576
#define OFF_BX   24576u    // u64[16 nt][32]          4096
#define OFF_BXN  28672u    // u64[8 nt][32]           2048
#define OFF_HS   30720u    // float[4 quads][2][32][HP] 73728
#define OFF_BRZ  104448u   // float[128]
#define OFF_BNH  104960u   // float[64]
#define OFF_BNX  105216u   // float[64]
#define SMEM_TOTAL 105472

#define LO32(u) ((uint32_t)(u))
#define HI32(u) ((uint32_t)((u) >> 32))

__device__ __forceinline__ uint32_t pkh(__half a, __half b) {
    return (uint32_t)*(uint16_t*)&a | ((uint32_t)*(uint16_t*)&b << 16);
}
__device__ __forceinline__ void hsplit2(float a, float b, uint32_t& hi, uint32_t& lo) {
    __half ah = __float2half_rn(a), bh = __float2half_rn(b);
    __half al = __float2half_rn(a - __half2float(ah));
    __half bl = __float2half_rn(b - __half2float(bh));
    hi = pkh(ah, bh);
    lo = pkh(al, bl);
}
__device__ __forceinline__ uint32_t hpack2(float a, float b) {
    __half2 h2 = __floats2half2_rn(a, b);
    return *(uint32_t*)&h2;
}
__device__ __forceinline__ void mma16(float* d, const uint32_t* a, uint32_t b0, uint32_t b1) {
    asm("mma.sync.aligned.m16n8k16.row.col.f32.f16.f16.f32 "
        "{%0,%1,%2,%3}, {%4,%5,%6,%7}, {%8,%9}, {%0,%1,%2,%3};"
        : "+f"(d[0]), "+f"(d[1]), "+f"(d[2]), "+f"(d[3])
        : "r"(a[0]), "r"(a[1]), "r"(a[2]), "r"(a[3]), "r"(b0), "r"(b1));
}
__device__ __forceinline__ float tanh_apx(float v) {
    float y; asm("tanh.approx.f32 %0, %1;" : "=f"(y) : "f"(v)); return y;
}
__device__ __forceinline__ float sig_t(float v) {
    return fmaf(tanh_apx(0.5f * v), 0.5f, 0.5f);
}

__global__ __launch_bounds__(THREADS, 1)
void gru_q4(const float* __restrict__ x, const float* __restrict__ w_ih,
            const float* __restrict__ w_hh, const float* __restrict__ b_ih,
            const float* __restrict__ b_hh, float* __restrict__ out)
{
    extern __shared__ char sm[];
    uint64_t* BB  = (uint64_t*)(sm + OFF_BB);
    uint64_t* BX  = (uint64_t*)(sm + OFF_BX);
    uint64_t* BXN = (uint64_t*)(sm + OFF_BXN);
    float* HS  = (float*)(sm + OFF_HS);
    float* BRZ = (float*)(sm + OFF_BRZ);
    float* BNH = (float*)(sm + OFF_BNH);
    float* BNX = (float*)(sm + OFF_BNX);

    const int tid = threadIdx.x, lane = tid & 31, warp = tid >> 5;

    // ================= one-time init =================
    for (int idx = tid; idx < 24 * 4 * 32; idx += THREADS) {
        int nt = idx >> 7, kt = (idx >> 5) & 3, le = idx & 31;
        int n = nt * 8 + (le >> 2), k0 = kt * 16 + 2 * (le & 3);
        uint32_t h01, l01, h89, l89;
        hsplit2(w_hh[n * 64 + k0],     w_hh[n * 64 + k0 + 1], h01, l01);
        hsplit2(w_hh[n * 64 + k0 + 8], w_hh[n * 64 + k0 + 9], h89, l89);
        BB[idx] = (uint64_t)h01 | ((uint64_t)h89 << 32);
    }
    for (int idx = tid; idx < 16 * 32; idx += THREADS) {
        int nt = idx >> 5, le = idx & 31, c = le & 3;
        int n = nt * 8 + (le >> 2), cc = 2 * (c & 1);
        uint32_t hi, lo;
        hsplit2(w_ih[n * 4 + cc], w_ih[n * 4 + cc + 1], hi, lo);
        BX[idx] = (uint64_t)hi | ((uint64_t)((c < 2) ? lo : 0u) << 32);
    }
    for (int idx = tid; idx < 8 * 32; idx += THREADS) {
        int nt = idx >> 5, le = idx & 31, c = le & 3;
        int n = 128 + nt * 8 + (le >> 2), cc = 2 * (c & 1);
        uint32_t hi, lo;
        hsplit2(w_ih[n * 4 + cc], w_ih[n * 4 + cc + 1], hi, lo);
        BXN[idx] = (uint64_t)hi | ((uint64_t)((c < 2) ? lo : 0u) << 32);
    }
    for (int idx = tid; idx < 4 * 2 * 32 * HP; idx += THREADS) HS[idx] = 0.0f;
    for (int idx = tid; idx < 128; idx += THREADS) BRZ[idx] = b_ih[idx] + b_hh[idx];
    if (tid < 64) { BNH[tid] = b_hh[128 + tid]; BNX[tid] = b_ih[128 + tid]; }
    __syncthreads();

    // ================= per-warp geometry =================
    const int quad = warp >> 2, w4 = warp & 3;
    const int base = (blockIdx.x * 4 + quad) * 32;
    float* hs0 = HS + quad * (2 * 32 * HP);
    const int g = lane >> 2, c = lane & 3;
    const int u0 = 2 * c, cc = 2 * (c & 1);
    const int j0 = 2 * w4;                 // own unit-blocks (== A k-tile w4)

    // x rows: i = mh*2 + rh -> row base + mh*16 + rh*8 + g (compile-time offsets)
    const float* __restrict__ xb = x + ((size_t)(base + g) * T_STEPS) * 4 + cc;
    const size_t XR8 = (size_t)8 * T_STEPS * 4;
    float2 xq[4];
#pragma unroll
    for (int i = 0; i < 4; i++) xq[i] = *(const float2*)(xb + (size_t)i * XR8);

    // hold[jj][mh][e]: units {(j0+jj)*8+u0,+1}, rows (mh*16+g | +8)
    float hold[2][2][4];
#pragma unroll
    for (int jj = 0; jj < 2; jj++)
#pragma unroll
        for (int mh = 0; mh < 2; mh++)
#pragma unroll
            for (int e = 0; e < 4; e++) hold[jj][mh][e] = 0.0f;

    uint32_t Ahq[4][2][4], Ax[2][4];   // Ahq[i] = ktile (w4+i)&3; i=0 own

    for (int t = 0; t < T_STEPS; t++) {
        const float* hrd = hs0 + (t & 1) * (32 * HP);
        float*       hwr = hs0 + ((t & 1) ^ 1) * (32 * HP);

        // ---- own k-tile from hold regs (D->A identity; jj=0 even j -> a0/a1) ----
#pragma unroll
        for (int mh = 0; mh < 2; mh++) {
            Ahq[0][mh][0] = hpack2(hold[0][mh][0], hold[0][mh][1]);
            Ahq[0][mh][1] = hpack2(hold[0][mh][2], hold[0][mh][3]);
            Ahq[0][mh][2] = hpack2(hold[1][mh][0], hold[1][mh][1]);
            Ahq[0][mh][3] = hpack2(hold[1][mh][2], hold[1][mh][3]);
        }
        // ---- partner k-tiles from smem (runtime ktile id in ADDRESS only) ----
#pragma unroll
        for (int i = 1; i < 4; i++) {
            const int kt = (w4 + i) & 3;
#pragma unroll
            for (int mh = 0; mh < 2; mh++) {
                const float* r0 = hrd + (mh * 16 + g) * HP + kt * 16 + u0;
                const float* r8 = r0 + 8 * HP;
                float2 v0 = *(const float2*)r0;
                float2 v8 = *(const float2*)r8;
                float2 w0 = *(const float2*)(r0 + 8);
                float2 w8 = *(const float2*)(r8 + 8);
                Ahq[i][mh][0] = hpack2(v0.x, v0.y);
                Ahq[i][mh][1] = hpack2(v8.x, v8.y);
                Ahq[i][mh][2] = hpack2(w0.x, w0.y);
                Ahq[i][mh][3] = hpack2(w8.x, w8.y);
            }
        }
        // ---- x frags (3-term fold inside one k16 tile) ----
#pragma unroll
        for (int mh = 0; mh < 2; mh++) {
            uint32_t ha_, la_, hb_, lb_;
            hsplit2(xq[2 * mh].x,     xq[2 * mh].y,     ha_, la_);
            hsplit2(xq[2 * mh + 1].x, xq[2 * mh + 1].y, hb_, lb_);
            Ax[mh][0] = (c < 2) ? ha_ : la_;
            Ax[mh][1] = (c < 2) ? hb_ : lb_;
            Ax[mh][2] = (c < 2) ? ha_ : 0u;
            Ax[mh][3] = (c < 2) ? hb_ : 0u;
        }
        if (t + 1 < T_STEPS) {
#pragma unroll
            for (int i = 0; i < 4; i++)
                xq[i] = *(const float2*)(xb + (size_t)i * XR8 + (size_t)(t + 1) * 4);
        }

        // ---- own 2 unit-blocks x 2 m-halves ----
#pragma unroll
        for (int jj = 0; jj < 2; jj++) {
            const int j = j0 + jj;
            float dr[2][4] = {}, dz[2][4] = {}, dn[2][4] = {}, dx[2][4] = {};
#pragma unroll
            for (int i = 0; i < 4; i++) {
                const int kt = (w4 + i) & 3;
                uint64_t br = BB[(j * 4 + kt) * 32 + lane];
                uint64_t bz = BB[((8 + j) * 4 + kt) * 32 + lane];
                uint64_t bn = BB[((16 + j) * 4 + kt) * 32 + lane];
#pragma unroll
                for (int mh = 0; mh < 2; mh++) {
                    mma16(dr[mh], Ahq[i][mh], LO32(br), HI32(br));
                    mma16(dz[mh], Ahq[i][mh], LO32(bz), HI32(bz));
                    mma16(dn[mh], Ahq[i][mh], LO32(bn), HI32(bn));
                }
            }
            {
                uint64_t bxr = BX[j * 32 + lane];
                uint64_t bxz = BX[(8 + j) * 32 + lane];
                uint64_t bxn = BXN[j * 32 + lane];
#pragma unroll
                for (int mh = 0; mh < 2; mh++) {
                    mma16(dr[mh], Ax[mh], LO32(bxr), HI32(bxr));
                    mma16(dz[mh], Ax[mh], LO32(bxz), HI32(bxz));
                    mma16(dx[mh], Ax[mh], LO32(bxn), HI32(bxn));
                }
            }
            // ---- epilogue (old h from regs; h' -> regs + smem for partners) ----
            float2 b_r = *(const float2*)(BRZ + j * 8 + u0);
            float2 b_z = *(const float2*)(BRZ + 64 + j * 8 + u0);
            float2 b_h = *(const float2*)(BNH + j * 8 + u0);
            float2 b_x = *(const float2*)(BNX + j * 8 + u0);
#pragma unroll
            for (int mh = 0; mh < 2; mh++) {
#pragma unroll
                for (int e = 0; e < 4; e++) {
                    float brv = (e & 1) ? b_r.y : b_r.x;
                    float bzv = (e & 1) ? b_z.y : b_z.x;
                    float bhv = (e & 1) ? b_h.y : b_h.x;
                    float bxv = (e & 1) ? b_x.y : b_x.x;
                    float r = sig_t(dr[mh][e] + brv);
                    float z = sig_t(dz[mh][e] + bzv);
                    float n = tanh_apx(fmaf(r, dn[mh][e] + bhv, dx[mh][e] + bxv));
                    hold[jj][mh][e] = fmaf(z, hold[jj][mh][e] - n, n);
                }
                float* wa = hwr + (mh * 16 + g) * HP + j * 8 + u0;
                *(float2*)wa            = make_float2(hold[jj][mh][0], hold[jj][mh][1]);
                *(float2*)(wa + 8 * HP) = make_float2(hold[jj][mh][2], hold[jj][mh][3]);
            }
        }

        // quad barrier: h' writes visible before next step's partner-tile reads
        asm volatile("bar.sync %0, %1;" :: "r"(quad + 1), "r"(128) : "memory");
    }

    // ---- output straight from hold regs ----
#pragma unroll
    for (int jj = 0; jj < 2; jj++) {
        const int j = j0 + jj;
#pragma unroll
        for (int mh = 0; mh < 2; mh++) {
            const int row = base + mh * 16 + g;
            *(float2*)(out + (size_t)row * 64 + j * 8 + u0) =
                make_float2(hold[jj][mh][0], hold[jj][mh][1]);
            *(float2*)(out + (size_t)(row + 8) * 64 + j * 8 + u0) =
                make_float2(hold[jj][mh][2], hold[jj][mh][3]);
        }
    }
}

extern "C" void kernel_launch(void* const* d_in, const int* in_sizes, int n_in,
                              void* d_out, int out_size)
{
    const float* x    = (const float*)d_in[0];
    const float* w_ih = (const float*)d_in[1];
    const float* w_hh = (const float*)d_in[2];
    const float* b_ih = (const float*)d_in[3];
    const float* b_hh = (const float*)d_in[4];
    float* out = (float*)d_out;

    cudaFuncSetAttribute(gru_q4, cudaFuncAttributeMaxDynamicSharedMemorySize, SMEM_TOTAL);
    gru_q4<<<128, THREADS, SMEM_TOTAL>>>(x, w_ih, w_hh, b_ih, b_hh, out);
}